// round 4
// baseline (speedup 1.0000x reference)
#include <cuda_runtime.h>
#include <cstdint>

// ---------------------------------------------------------------------------
// MultiRectSDF: out[i] = min over 32 shapes of rotated-rect SDF at query[i].
// Compute-bound (fma-pipe). Uses packed fma.rn.f32x2 for the rotation
// (the dominant FFMA cost), scalar FADD|abs| / FMNMX / MUFU.SQRT for the rest.
// ---------------------------------------------------------------------------

static __device__ __forceinline__ unsigned long long pack2(float lo, float hi) {
    unsigned long long r;
    asm("mov.b64 %0, {%1, %2};" : "=l"(r) : "r"(__float_as_uint(lo)), "r"(__float_as_uint(hi)));
    return r;
}

static __device__ __forceinline__ void unpack2(unsigned long long v, float& lo, float& hi) {
    unsigned int a, b;
    asm("mov.b64 {%0, %1}, %2;" : "=r"(a), "=r"(b) : "l"(v));
    lo = __uint_as_float(a);
    hi = __uint_as_float(b);
}

static __device__ __forceinline__ unsigned long long ffma2(
    unsigned long long a, unsigned long long b, unsigned long long c) {
    unsigned long long d;
    asm("fma.rn.f32x2 %0, %1, %2, %3;" : "=l"(d) : "l"(a), "l"(b), "l"(c));
    return d;
}

static __device__ __forceinline__ float fsqrt_approx(float x) {
    float y;
    asm("sqrt.approx.f32 %0, %1;" : "=f"(y) : "f"(x));
    return y;
}

struct __align__(16) ShapeConst {
    unsigned long long cP, sP, nsP, ntxP, ntyP;  // duplicated packed (v,v)
    float nrx, nry;                              // negated half-extents
};

static constexpr int NSHAPES = 32;
static constexpr int PTS_PER_THREAD = 8;   // 2 float4 loads, 4 packed pairs
static constexpr int BLOCK = 256;

__global__ __launch_bounds__(BLOCK)
void multirect_sdf_fast(const float* __restrict__ query,
                        const float* __restrict__ trans,
                        const float* __restrict__ rads,
                        const float* __restrict__ angles,
                        float* __restrict__ out) {
    __shared__ ShapeConst sc[NSHAPES];

    // Per-block shape-constant prep (32 threads, ~2 MUFU each — negligible).
    if (threadIdx.x < NSHAPES) {
        const int i = threadIdx.x;
        float s, c;
        __sincosf(angles[i], &s, &c);   // |angle| <= 0.1 -> ~1e-7 abs error
        const float tx = trans[2 * i + 0];
        const float ty = trans[2 * i + 1];
        sc[i].cP   = pack2(c, c);
        sc[i].sP   = pack2(s, s);
        sc[i].nsP  = pack2(-s, -s);
        sc[i].ntxP = pack2(-tx, -tx);
        sc[i].ntyP = pack2(-ty, -ty);
        sc[i].nrx  = -rads[2 * i + 0];
        sc[i].nry  = -rads[2 * i + 1];
    }
    __syncthreads();

    const int tid = blockIdx.x * BLOCK + threadIdx.x;

    // Load 8 points = 2x float4 (layout: x0 y0 x1 y1 ...)
    const float4* q4 = reinterpret_cast<const float4*>(query);
    float4 q[4];
#pragma unroll
    for (int k = 0; k < 4; k++) q[k] = q4[tid * 4 + k];

    unsigned long long X[4], Y[4];
#pragma unroll
    for (int k = 0; k < 4; k++) {
        X[k] = pack2(q[k].x, q[k].z);
        Y[k] = pack2(q[k].y, q[k].w);
    }

    float best[PTS_PER_THREAD];
#pragma unroll
    for (int p = 0; p < PTS_PER_THREAD; p++) best[p] = 3.0e38f;

#pragma unroll 4
    for (int i = 0; i < NSHAPES; i++) {
        const ShapeConst k = sc[i];   // 3x LDS.128
#pragma unroll
        for (int p = 0; p < 4; p++) {
            // Packed rotation + translation: 4 FFMA2 for 2 points.
            unsigned long long RX = ffma2(k.cP, X[p], ffma2(k.nsP, Y[p], k.ntxP));
            unsigned long long RY = ffma2(k.sP, X[p], ffma2(k.cP, Y[p], k.ntyP));
            float rx0, rx1, ry0, ry1;
            unpack2(RX, rx0, rx1);
            unpack2(RY, ry0, ry1);

            {
                const float dx = fabsf(rx0) + k.nrx;      // FADD |src|
                const float dy = fabsf(ry0) + k.nry;
                const float mx = fmaxf(dx, 0.0f);
                const float my = fmaxf(dy, 0.0f);
                const float sq = fmaf(mx, mx, my * my);
                const float o  = fsqrt_approx(sq);        // sqrt(0) == 0 matches ref
                const float in = fminf(fmaxf(dx, dy), 0.0f);
                best[2 * p + 0] = fminf(best[2 * p + 0], o + in);
            }
            {
                const float dx = fabsf(rx1) + k.nrx;
                const float dy = fabsf(ry1) + k.nry;
                const float mx = fmaxf(dx, 0.0f);
                const float my = fmaxf(dy, 0.0f);
                const float sq = fmaf(mx, mx, my * my);
                const float o  = fsqrt_approx(sq);
                const float in = fminf(fmaxf(dx, dy), 0.0f);
                best[2 * p + 1] = fminf(best[2 * p + 1], o + in);
            }
        }
    }

    float4* o4 = reinterpret_cast<float4*>(out);
    o4[tid * 2 + 0] = make_float4(best[0], best[1], best[2], best[3]);
    o4[tid * 2 + 1] = make_float4(best[4], best[5], best[6], best[7]);
}

// Generic fallback (any n, any shape count) — correctness safety net.
__global__ void multirect_sdf_generic(const float* __restrict__ query,
                                      const float* __restrict__ trans,
                                      const float* __restrict__ rads,
                                      const float* __restrict__ angles,
                                      float* __restrict__ out,
                                      int n, int ns) {
    const int i = blockIdx.x * blockDim.x + threadIdx.x;
    if (i >= n) return;
    const float qx = query[2 * i + 0];
    const float qy = query[2 * i + 1];
    float best = 3.0e38f;
    for (int s = 0; s < ns; s++) {
        float sn, c;
        __sincosf(angles[s], &sn, &c);
        const float rx = fmaf(c, qx, fmaf(-sn, qy, -trans[2 * s + 0]));
        const float ry = fmaf(sn, qx, fmaf(c, qy, -trans[2 * s + 1]));
        const float dx = fabsf(rx) - rads[2 * s + 0];
        const float dy = fabsf(ry) - rads[2 * s + 1];
        const float mx = fmaxf(dx, 0.0f);
        const float my = fmaxf(dy, 0.0f);
        const float o  = fsqrt_approx(fmaf(mx, mx, my * my));
        const float in = fminf(fmaxf(dx, dy), 0.0f);
        best = fminf(best, o + in);
    }
    out[i] = best;
}

extern "C" void kernel_launch(void* const* d_in, const int* in_sizes, int n_in,
                              void* d_out, int out_size) {
    const float* query  = (const float*)d_in[0];  // (N, 2) fp32
    const float* trans  = (const float*)d_in[1];  // (S, 2) fp32
    const float* rads   = (const float*)d_in[2];  // (S, 2) fp32
    const float* angles = (const float*)d_in[3];  // (S,)  fp32
    float* out = (float*)d_out;

    const int n  = in_sizes[0] / 2;
    const int ns = in_sizes[3];

    if (ns == NSHAPES && (n % PTS_PER_THREAD) == 0 &&
        ((n / PTS_PER_THREAD) % BLOCK) == 0) {
        const int threads = n / PTS_PER_THREAD;
        multirect_sdf_fast<<<threads / BLOCK, BLOCK>>>(query, trans, rads, angles, out);
    } else {
        const int blk = 256;
        multirect_sdf_generic<<<(n + blk - 1) / blk, blk>>>(query, trans, rads, angles,
                                                            out, n, ns);
    }
}

// round 5
// speedup vs baseline: 1.0085x; 1.0085x over previous
#include <cuda_runtime.h>
#include <cstdint>

// ---------------------------------------------------------------------------
// MultiRectSDF: out[i] = min over 32 shapes of rotated-rect SDF at query[i].
//
// Restructured: track minSq = min_i (relu(dx)^2 + relu(dy)^2) and
//               minM  = min_i max(dx, dy)
// then final = (minM < 0) ? minM : sqrt(minSq).
// This hoists sqrt + the outside/inside combine out of the shape loop:
// loop body = 12 fma-pipe + 10 alu-pipe instrs per packed point-pair.
// Rotation uses packed fma.rn.f32x2 (FFMA2), everything else scalar to keep
// abs folded into FADD and the two fixed pipes balanced.
// ---------------------------------------------------------------------------

static __device__ __forceinline__ unsigned long long pack2(float lo, float hi) {
    unsigned long long r;
    asm("mov.b64 %0, {%1, %2};" : "=l"(r) : "r"(__float_as_uint(lo)), "r"(__float_as_uint(hi)));
    return r;
}

static __device__ __forceinline__ void unpack2(unsigned long long v, float& lo, float& hi) {
    unsigned int a, b;
    asm("mov.b64 {%0, %1}, %2;" : "=r"(a), "=r"(b) : "l"(v));
    lo = __uint_as_float(a);
    hi = __uint_as_float(b);
}

static __device__ __forceinline__ unsigned long long ffma2(
    unsigned long long a, unsigned long long b, unsigned long long c) {
    unsigned long long d;
    asm("fma.rn.f32x2 %0, %1, %2, %3;" : "=l"(d) : "l"(a), "l"(b), "l"(c));
    return d;
}

static __device__ __forceinline__ float fsqrt_approx(float x) {
    float y;
    asm("sqrt.approx.f32 %0, %1;" : "=f"(y) : "f"(x));
    return y;
}

struct __align__(16) ShapeConst {
    unsigned long long cP, sP, nsP, ntxP, ntyP;  // duplicated packed (v,v)
    float nrx, nry;                              // negated half-extents
};  // 48 bytes -> 3x LDS.128 per shape

static constexpr int NSHAPES = 32;
static constexpr int PTS_PER_THREAD = 4;   // 1 float4-pair of input, 2 packed pairs
static constexpr int BLOCK = 256;

__global__ __launch_bounds__(BLOCK, 5)
void multirect_sdf_fast(const float* __restrict__ query,
                        const float* __restrict__ trans,
                        const float* __restrict__ rads,
                        const float* __restrict__ angles,
                        float* __restrict__ out) {
    __shared__ ShapeConst sc[NSHAPES];

    if (threadIdx.x < NSHAPES) {
        const int i = threadIdx.x;
        float s, c;
        __sincosf(angles[i], &s, &c);
        const float tx = trans[2 * i + 0];
        const float ty = trans[2 * i + 1];
        sc[i].cP   = pack2(c, c);
        sc[i].sP   = pack2(s, s);
        sc[i].nsP  = pack2(-s, -s);
        sc[i].ntxP = pack2(-tx, -tx);
        sc[i].ntyP = pack2(-ty, -ty);
        sc[i].nrx  = -rads[2 * i + 0];
        sc[i].nry  = -rads[2 * i + 1];
    }
    __syncthreads();

    const int tid = blockIdx.x * BLOCK + threadIdx.x;

    // 4 points = 2x float4 (layout: x0 y0 x1 y1 x2 y2 x3 y3)
    const float4* q4 = reinterpret_cast<const float4*>(query);
    const float4 qa = q4[tid * 2 + 0];
    const float4 qb = q4[tid * 2 + 1];

    unsigned long long X[2], Y[2];
    X[0] = pack2(qa.x, qa.z);  Y[0] = pack2(qa.y, qa.w);
    X[1] = pack2(qb.x, qb.z);  Y[1] = pack2(qb.y, qb.w);

    float minSq[PTS_PER_THREAD], minM[PTS_PER_THREAD];
#pragma unroll
    for (int p = 0; p < PTS_PER_THREAD; p++) {
        minSq[p] = 3.0e38f;
        minM[p]  = 3.0e38f;
    }

#pragma unroll 8
    for (int i = 0; i < NSHAPES; i++) {
        const ShapeConst k = sc[i];
#pragma unroll
        for (int pr = 0; pr < 2; pr++) {
            // Packed rotation + translation: 4 FFMA2 per point-pair.
            const unsigned long long RX = ffma2(k.cP, X[pr], ffma2(k.nsP, Y[pr], k.ntxP));
            const unsigned long long RY = ffma2(k.sP, X[pr], ffma2(k.cP, Y[pr], k.ntyP));
            float rx0, rx1, ry0, ry1;
            unpack2(RX, rx0, rx1);
            unpack2(RY, ry0, ry1);

            {
                const float dx = fabsf(rx0) + k.nrx;     // FADD with |src|
                const float dy = fabsf(ry0) + k.nry;
                const float mx = fmaxf(dx, 0.0f);
                const float my = fmaxf(dy, 0.0f);
                const float sq = fmaf(mx, mx, my * my);
                minSq[2 * pr + 0] = fminf(minSq[2 * pr + 0], sq);
                minM[2 * pr + 0]  = fminf(minM[2 * pr + 0], fmaxf(dx, dy));
            }
            {
                const float dx = fabsf(rx1) + k.nrx;
                const float dy = fabsf(ry1) + k.nry;
                const float mx = fmaxf(dx, 0.0f);
                const float my = fmaxf(dy, 0.0f);
                const float sq = fmaf(mx, mx, my * my);
                minSq[2 * pr + 1] = fminf(minSq[2 * pr + 1], sq);
                minM[2 * pr + 1]  = fminf(minM[2 * pr + 1], fmaxf(dx, dy));
            }
        }
    }

    // Epilogue: sqrt + inside/outside select, once per point.
    float res[PTS_PER_THREAD];
#pragma unroll
    for (int p = 0; p < PTS_PER_THREAD; p++) {
        const float o = fsqrt_approx(minSq[p]);   // sqrt(0) == 0 matches ref
        res[p] = (minM[p] < 0.0f) ? minM[p] : o;
    }

    float4* o4 = reinterpret_cast<float4*>(out);
    o4[tid] = make_float4(res[0], res[1], res[2], res[3]);
}

// Generic fallback (any n, any shape count) — correctness safety net.
__global__ void multirect_sdf_generic(const float* __restrict__ query,
                                      const float* __restrict__ trans,
                                      const float* __restrict__ rads,
                                      const float* __restrict__ angles,
                                      float* __restrict__ out,
                                      int n, int ns) {
    const int i = blockIdx.x * blockDim.x + threadIdx.x;
    if (i >= n) return;
    const float qx = query[2 * i + 0];
    const float qy = query[2 * i + 1];
    float best = 3.0e38f;
    for (int s = 0; s < ns; s++) {
        float sn, c;
        __sincosf(angles[s], &sn, &c);
        const float rx = fmaf(c, qx, fmaf(-sn, qy, -trans[2 * s + 0]));
        const float ry = fmaf(sn, qx, fmaf(c, qy, -trans[2 * s + 1]));
        const float dx = fabsf(rx) - rads[2 * s + 0];
        const float dy = fabsf(ry) - rads[2 * s + 1];
        const float mx = fmaxf(dx, 0.0f);
        const float my = fmaxf(dy, 0.0f);
        const float o  = fsqrt_approx(fmaf(mx, mx, my * my));
        const float in = fminf(fmaxf(dx, dy), 0.0f);
        best = fminf(best, o + in);
    }
    out[i] = best;
}

extern "C" void kernel_launch(void* const* d_in, const int* in_sizes, int n_in,
                              void* d_out, int out_size) {
    const float* query  = (const float*)d_in[0];  // (N, 2) fp32
    const float* trans  = (const float*)d_in[1];  // (S, 2) fp32
    const float* rads   = (const float*)d_in[2];  // (S, 2) fp32
    const float* angles = (const float*)d_in[3];  // (S,)  fp32
    float* out = (float*)d_out;

    const int n  = in_sizes[0] / 2;
    const int ns = in_sizes[3];

    if (ns == NSHAPES && (n % PTS_PER_THREAD) == 0 &&
        ((n / PTS_PER_THREAD) % BLOCK) == 0) {
        const int threads = n / PTS_PER_THREAD;
        multirect_sdf_fast<<<threads / BLOCK, BLOCK>>>(query, trans, rads, angles, out);
    } else {
        const int blk = 256;
        multirect_sdf_generic<<<(n + blk - 1) / blk, blk>>>(query, trans, rads, angles,
                                                            out, n, ns);
    }
}

// round 8
// speedup vs baseline: 1.1949x; 1.1848x over previous
#include <cuda_runtime.h>
#include <cstdint>

// ---------------------------------------------------------------------------
// MultiRectSDF: out[i] = min over 32 shapes of rotated-rect SDF at query[i].
//
// R6 = R2's 8-points/thread (keeps shared-const LDS traffic amortized; R5's
// 4-pt variant doubled LDS and stalled the LSU) + R5's restructure:
//   minSq = min_i (relu(dx)^2 + relu(dy)^2),  minM = min_i max(dx,dy)
//   final = (minM < 0) ? minM : sqrt(minSq)
// which keeps sqrt + the inside/outside combine out of the 32-shape loop.
// Rotation uses packed fma.rn.f32x2; the rest is scalar to keep |src| folded
// into FADD and the fma/alu pipes balanced.
// (Resubmission of R6 — prior round was a GB300 container infra failure.)
// ---------------------------------------------------------------------------

static __device__ __forceinline__ unsigned long long pack2(float lo, float hi) {
    unsigned long long r;
    asm("mov.b64 %0, {%1, %2};" : "=l"(r) : "r"(__float_as_uint(lo)), "r"(__float_as_uint(hi)));
    return r;
}

static __device__ __forceinline__ void unpack2(unsigned long long v, float& lo, float& hi) {
    unsigned int a, b;
    asm("mov.b64 {%0, %1}, %2;" : "=r"(a), "=r"(b) : "l"(v));
    lo = __uint_as_float(a);
    hi = __uint_as_float(b);
}

static __device__ __forceinline__ unsigned long long ffma2(
    unsigned long long a, unsigned long long b, unsigned long long c) {
    unsigned long long d;
    asm("fma.rn.f32x2 %0, %1, %2, %3;" : "=l"(d) : "l"(a), "l"(b), "l"(c));
    return d;
}

static __device__ __forceinline__ float fsqrt_approx(float x) {
    float y;
    asm("sqrt.approx.f32 %0, %1;" : "=f"(y) : "f"(x));
    return y;
}

struct __align__(16) ShapeConst {
    unsigned long long cP, sP, nsP, ntxP, ntyP;  // duplicated packed (v,v)
    float nrx, nry;                              // negated half-extents
};  // 48 bytes -> 3x LDS.128 per shape

static constexpr int NSHAPES = 32;
static constexpr int PTS_PER_THREAD = 8;   // 2x float4 in, 4 packed pairs
static constexpr int BLOCK = 256;

__global__ __launch_bounds__(BLOCK)
void multirect_sdf_fast(const float* __restrict__ query,
                        const float* __restrict__ trans,
                        const float* __restrict__ rads,
                        const float* __restrict__ angles,
                        float* __restrict__ out) {
    __shared__ ShapeConst sc[NSHAPES];

    if (threadIdx.x < NSHAPES) {
        const int i = threadIdx.x;
        float s, c;
        __sincosf(angles[i], &s, &c);   // |angle| <= 0.1 -> ~1e-7 abs error
        const float tx = trans[2 * i + 0];
        const float ty = trans[2 * i + 1];
        sc[i].cP   = pack2(c, c);
        sc[i].sP   = pack2(s, s);
        sc[i].nsP  = pack2(-s, -s);
        sc[i].ntxP = pack2(-tx, -tx);
        sc[i].ntyP = pack2(-ty, -ty);
        sc[i].nrx  = -rads[2 * i + 0];
        sc[i].nry  = -rads[2 * i + 1];
    }
    __syncthreads();

    const int tid = blockIdx.x * BLOCK + threadIdx.x;

    // 8 points = 4x float4 (layout: x0 y0 x1 y1 ...)
    const float4* q4 = reinterpret_cast<const float4*>(query);
    float4 q[4];
#pragma unroll
    for (int k = 0; k < 4; k++) q[k] = q4[tid * 4 + k];

    unsigned long long X[4], Y[4];
#pragma unroll
    for (int k = 0; k < 4; k++) {
        X[k] = pack2(q[k].x, q[k].z);
        Y[k] = pack2(q[k].y, q[k].w);
    }

    float minSq[PTS_PER_THREAD], minM[PTS_PER_THREAD];
#pragma unroll
    for (int p = 0; p < PTS_PER_THREAD; p++) {
        minSq[p] = 3.0e38f;
        minM[p]  = 3.0e38f;
    }

#pragma unroll 4
    for (int i = 0; i < NSHAPES; i++) {
        const ShapeConst k = sc[i];   // 3x LDS.128, amortized over 4 pairs
#pragma unroll
        for (int pr = 0; pr < 4; pr++) {
            // Packed rotation + translation: 4 FFMA2 per point-pair.
            const unsigned long long RX = ffma2(k.cP, X[pr], ffma2(k.nsP, Y[pr], k.ntxP));
            const unsigned long long RY = ffma2(k.sP, X[pr], ffma2(k.cP, Y[pr], k.ntyP));
            float rx0, rx1, ry0, ry1;
            unpack2(RX, rx0, rx1);
            unpack2(RY, ry0, ry1);

            {
                const float dx = fabsf(rx0) + k.nrx;     // FADD with |src|
                const float dy = fabsf(ry0) + k.nry;
                const float mx = fmaxf(dx, 0.0f);
                const float my = fmaxf(dy, 0.0f);
                const float sq = fmaf(mx, mx, my * my);
                minSq[2 * pr + 0] = fminf(minSq[2 * pr + 0], sq);
                minM[2 * pr + 0]  = fminf(minM[2 * pr + 0], fmaxf(dx, dy));
            }
            {
                const float dx = fabsf(rx1) + k.nrx;
                const float dy = fabsf(ry1) + k.nry;
                const float mx = fmaxf(dx, 0.0f);
                const float my = fmaxf(dy, 0.0f);
                const float sq = fmaf(mx, mx, my * my);
                minSq[2 * pr + 1] = fminf(minSq[2 * pr + 1], sq);
                minM[2 * pr + 1]  = fminf(minM[2 * pr + 1], fmaxf(dx, dy));
            }
        }
    }

    // Epilogue: sqrt + inside/outside select, once per point (amortized 32x).
    float res[PTS_PER_THREAD];
#pragma unroll
    for (int p = 0; p < PTS_PER_THREAD; p++) {
        const float o = fsqrt_approx(minSq[p]);   // sqrt(0) == 0 matches ref
        res[p] = (minM[p] < 0.0f) ? minM[p] : o;
    }

    float4* o4 = reinterpret_cast<float4*>(out);
    o4[tid * 2 + 0] = make_float4(res[0], res[1], res[2], res[3]);
    o4[tid * 2 + 1] = make_float4(res[4], res[5], res[6], res[7]);
}

// Generic fallback (any n, any shape count) — correctness safety net.
__global__ void multirect_sdf_generic(const float* __restrict__ query,
                                      const float* __restrict__ trans,
                                      const float* __restrict__ rads,
                                      const float* __restrict__ angles,
                                      float* __restrict__ out,
                                      int n, int ns) {
    const int i = blockIdx.x * blockDim.x + threadIdx.x;
    if (i >= n) return;
    const float qx = query[2 * i + 0];
    const float qy = query[2 * i + 1];
    float best = 3.0e38f;
    for (int s = 0; s < ns; s++) {
        float sn, c;
        __sincosf(angles[s], &sn, &c);
        const float rx = fmaf(c, qx, fmaf(-sn, qy, -trans[2 * s + 0]));
        const float ry = fmaf(sn, qx, fmaf(c, qy, -trans[2 * s + 1]));
        const float dx = fabsf(rx) - rads[2 * s + 0];
        const float dy = fabsf(ry) - rads[2 * s + 1];
        const float mx = fmaxf(dx, 0.0f);
        const float my = fmaxf(dy, 0.0f);
        const float o  = fsqrt_approx(fmaf(mx, mx, my * my));
        const float in = fminf(fmaxf(dx, dy), 0.0f);
        best = fminf(best, o + in);
    }
    out[i] = best;
}

extern "C" void kernel_launch(void* const* d_in, const int* in_sizes, int n_in,
                              void* d_out, int out_size) {
    const float* query  = (const float*)d_in[0];  // (N, 2) fp32
    const float* trans  = (const float*)d_in[1];  // (S, 2) fp32
    const float* rads   = (const float*)d_in[2];  // (S, 2) fp32
    const float* angles = (const float*)d_in[3];  // (S,)  fp32
    float* out = (float*)d_out;

    const int n  = in_sizes[0] / 2;
    const int ns = in_sizes[3];

    if (ns == NSHAPES && (n % PTS_PER_THREAD) == 0 &&
        ((n / PTS_PER_THREAD) % BLOCK) == 0) {
        const int threads = n / PTS_PER_THREAD;
        multirect_sdf_fast<<<threads / BLOCK, BLOCK>>>(query, trans, rads, angles, out);
    } else {
        const int blk = 256;
        multirect_sdf_generic<<<(n + blk - 1) / blk, blk>>>(query, trans, rads, angles,
                                                            out, n, ns);
    }
}